// round 1
// baseline (speedup 1.0000x reference)
#include <cuda_runtime.h>
#include <math.h>

// Problem dims
#define SEQ   512
#define BATCH 64
#define INPUT 256
#define HID   1024
#define KTOT  1280      // HID + INPUT (fused recurrent + input projection)
#define GATES 4

// Kernel config
#define NCTA  128       // persistent CTAs (<= 148 SMs, 1 CTA/SM by smem)
#define NTHR  256
#define JPC   8         // hidden units per CTA  (128*8 = 1024)
#define NC    32        // gate-columns per CTA  (4 gates * 8)
#define KC    128       // k-chunk staged in smem
#define WSTRIDE 34      // padded row stride for weight smem (kills bank conflicts)

// Scratch (static device globals — no allocation)
__device__ float    g_xT[(size_t)SEQ * INPUT * BATCH];   // x transposed: [t][k][b]
__device__ float    g_h[2 * HID * BATCH];                 // h double buffer, [buf][j][b]
__device__ unsigned g_bar;                                // global barrier counter

struct Params {
    const float* Wx[4];  // Wfx, Wix, Wgx, Wox   [1024,256]
    const float* bx[4];
    const float* Wh[4];  // Wfh, Wih, Wgh, Woh   [1024,1024]
    const float* bh[4];
    float* out;
};

// ---------------------------------------------------------------------------
// Init: zero h buffer 0 and the barrier counter (every launch -> graph-safe)
// ---------------------------------------------------------------------------
__global__ void init_kernel() {
    int i = blockIdx.x * blockDim.x + threadIdx.x;
    if (i < HID * BATCH) g_h[i] = 0.0f;
    if (i == 0) g_bar = 0u;
}

// ---------------------------------------------------------------------------
// Transpose x[t][b][k] -> g_xT[t][k][b]  (coalesced both sides via smem tile)
// grid (SEQ, 2), 256 threads; each block does 32 batches x 256 k of one t.
// ---------------------------------------------------------------------------
__global__ void transpose_kernel(const float* __restrict__ x) {
    __shared__ float tile[32 * 257];
    int t  = blockIdx.x;
    int b0 = blockIdx.y * 32;
    const float* src = x + (size_t)t * BATCH * INPUT;
    for (int idx = threadIdx.x; idx < 32 * INPUT; idx += blockDim.x) {
        int b = idx >> 8, k = idx & 255;
        tile[b * 257 + k] = src[(size_t)(b0 + b) * INPUT + k];
    }
    __syncthreads();
    float* dst = g_xT + (size_t)t * INPUT * BATCH;
    for (int idx = threadIdx.x; idx < 32 * INPUT; idx += blockDim.x) {
        int k = idx >> 5, b = idx & 31;
        dst[k * BATCH + b0 + b] = tile[b * 257 + k];
    }
}

// ---------------------------------------------------------------------------
// Persistent LSTM kernel. CTA cta owns hidden units [cta*8, cta*8+8).
// Weights for its 32 gate-columns (K=1280 each) stay in smem all 512 steps.
// c-state stays in registers. Global spin barrier per step.
// ---------------------------------------------------------------------------
__global__ __launch_bounds__(NTHR, 1)
void lstm_persistent(Params P) {
    extern __shared__ float smem[];
    float* wsm  = smem;                         // [KTOT][WSTRIDE]   174080 B
    float* hx   = wsm + KTOT * WSTRIDE;         // [KC][BATCH]        32768 B
    float* acts = hx + KC * BATCH;              // [NC][BATCH]         8192 B
    float* bsum = acts + NC * BATCH;            // [NC]                 128 B

    const int tid = threadIdx.x;
    const int cta = blockIdx.x;
    const int j0  = cta * JPC;

    // ---- load weight slice into smem (once per launch) ----
    for (int c = 0; c < NC; c++) {
        int gate = c >> 3, jl = c & 7, j = j0 + jl;
        const float* wh = P.Wh[gate] + (size_t)j * HID;
        const float* wx = P.Wx[gate] + (size_t)j * INPUT;
        for (int k = tid; k < HID; k += NTHR)
            wsm[k * WSTRIDE + c] = wh[k];
        for (int k = tid; k < INPUT; k += NTHR)
            wsm[(HID + k) * WSTRIDE + c] = wx[k];
    }
    if (tid < NC) {
        int gate = tid >> 3, jl = tid & 7, j = j0 + jl;
        bsum[tid] = P.bh[gate][j] + P.bx[gate][j];
    }

    const int tx = tid & 15;      // column pair  (2*tx, 2*tx+1)
    const int ty = tid >> 4;      // batch quad   (4*ty .. 4*ty+3)

    // pointwise cell mapping: cell cid = b*8 + jl ; thread owns cid 2t, 2t+1
    const int cid0 = 2 * tid, cid1 = 2 * tid + 1;
    const int pb0 = cid0 >> 3, pjl0 = cid0 & 7;
    const int pb1 = cid1 >> 3, pjl1 = cid1 & 7;
    float cs0 = 0.0f, cs1 = 0.0f;

    float* out = P.out;
    const size_t SBH = (size_t)SEQ * BATCH * HID;

    for (int t = 0; t < SEQ; t++) {
        const float* hprev = g_h + (t & 1) * HID * BATCH;
        float*       hnext = g_h + ((t + 1) & 1) * HID * BATCH;
        const float* xT    = g_xT + (size_t)t * INPUT * BATCH;

        float a00 = 0.f, a01 = 0.f, a10 = 0.f, a11 = 0.f;
        float a20 = 0.f, a21 = 0.f, a30 = 0.f, a31 = 0.f;

        for (int kc0 = 0; kc0 < KTOT; kc0 += KC) {
            __syncthreads();   // protect hx reuse
            #pragma unroll
            for (int i = 0; i < (KC * BATCH) / NTHR; i++) {
                int idx = tid + i * NTHR;
                int kk = idx >> 6, b = idx & 63;
                int k = kc0 + kk;
                hx[idx] = (k < HID) ? hprev[k * BATCH + b]
                                    : xT[(k - HID) * BATCH + b];
            }
            __syncthreads();

            const float* wp = wsm + (size_t)kc0 * WSTRIDE + tx * 2;
            const float* hp = hx + ty * 4;
            #pragma unroll 8
            for (int kk = 0; kk < KC; kk++) {
                float4 hv = *(const float4*)(hp + kk * BATCH);
                float2 wv = *(const float2*)(wp + kk * WSTRIDE);
                a00 += hv.x * wv.x;  a01 += hv.x * wv.y;
                a10 += hv.y * wv.x;  a11 += hv.y * wv.y;
                a20 += hv.z * wv.x;  a21 += hv.z * wv.y;
                a30 += hv.w * wv.x;  a31 += hv.w * wv.y;
            }
        }

        // scatter accumulators to acts[c][b]
        {
            float* ac = acts + (2 * tx) * BATCH + 4 * ty;
            ac[0] = a00; ac[1] = a10; ac[2] = a20; ac[3] = a30;
            ac += BATCH;
            ac[0] = a01; ac[1] = a11; ac[2] = a21; ac[3] = a31;
        }
        __syncthreads();

        // ---- pointwise gates for this CTA's 512 cells (2 per thread) ----
        {
            int b = pb0, jl = pjl0;
            float f  = acts[jl * BATCH + b]        + bsum[jl];
            float ii = acts[(8 + jl) * BATCH + b]  + bsum[8 + jl];
            float gg = acts[(16 + jl) * BATCH + b] + bsum[16 + jl];
            float oo = acts[(24 + jl) * BATCH + b] + bsum[24 + jl];
            f  = 1.0f / (1.0f + expf(-f));
            ii = 1.0f / (1.0f + expf(-ii));
            gg = tanhf(gg);
            oo = 1.0f / (1.0f + expf(-oo));
            cs0 = cs0 * f + ii * gg;
            float hv = tanhf(cs0) * oo;
            int j = j0 + jl;
            out[(size_t)t * BATCH * HID + (size_t)b * HID + j] = hv;
            hnext[j * BATCH + b] = hv;
            if (t == SEQ - 1) {
                out[SBH + (size_t)b * HID + j] = hv;
                out[SBH + (size_t)BATCH * HID + (size_t)b * HID + j] = cs0;
            }
        }
        {
            int b = pb1, jl = pjl1;
            float f  = acts[jl * BATCH + b]        + bsum[jl];
            float ii = acts[(8 + jl) * BATCH + b]  + bsum[8 + jl];
            float gg = acts[(16 + jl) * BATCH + b] + bsum[16 + jl];
            float oo = acts[(24 + jl) * BATCH + b] + bsum[24 + jl];
            f  = 1.0f / (1.0f + expf(-f));
            ii = 1.0f / (1.0f + expf(-ii));
            gg = tanhf(gg);
            oo = 1.0f / (1.0f + expf(-oo));
            cs1 = cs1 * f + ii * gg;
            float hv = tanhf(cs1) * oo;
            int j = j0 + jl;
            out[(size_t)t * BATCH * HID + (size_t)b * HID + j] = hv;
            hnext[j * BATCH + b] = hv;
            if (t == SEQ - 1) {
                out[SBH + (size_t)b * HID + j] = hv;
                out[SBH + (size_t)BATCH * HID + (size_t)b * HID + j] = cs1;
            }
        }

        // ---- grid-wide barrier (monotonic counter, reset each launch) ----
        __syncthreads();
        if (tid == 0) {
            __threadfence();
            atomicAdd(&g_bar, 1u);
            unsigned target = (unsigned)(t + 1) * NCTA;
            while (*((volatile unsigned*)&g_bar) < target) {
                __nanosleep(32);
            }
            __threadfence();
        }
        __syncthreads();
    }
}

// ---------------------------------------------------------------------------
// Launch
// ---------------------------------------------------------------------------
extern "C" void kernel_launch(void* const* d_in, const int* in_sizes, int n_in,
                              void* d_out, int out_size) {
    const float* x = (const float*)d_in[0];
    Params P;
    // order: Wfx,bfx, Wix,bix, Wgx,bgx, Wox,box, Wfh,bfh, Wih,bih, Wgh,bgh, Woh,boh
    P.Wx[0] = (const float*)d_in[1];  P.bx[0] = (const float*)d_in[2];
    P.Wx[1] = (const float*)d_in[3];  P.bx[1] = (const float*)d_in[4];
    P.Wx[2] = (const float*)d_in[5];  P.bx[2] = (const float*)d_in[6];
    P.Wx[3] = (const float*)d_in[7];  P.bx[3] = (const float*)d_in[8];
    P.Wh[0] = (const float*)d_in[9];  P.bh[0] = (const float*)d_in[10];
    P.Wh[1] = (const float*)d_in[11]; P.bh[1] = (const float*)d_in[12];
    P.Wh[2] = (const float*)d_in[13]; P.bh[2] = (const float*)d_in[14];
    P.Wh[3] = (const float*)d_in[15]; P.bh[3] = (const float*)d_in[16];
    P.out   = (float*)d_out;

    const int smem_bytes = (KTOT * WSTRIDE + KC * BATCH + NC * BATCH + NC) * 4;

    static bool attr_set = false;
    if (!attr_set) {
        cudaFuncSetAttribute(lstm_persistent,
                             cudaFuncAttributeMaxDynamicSharedMemorySize,
                             smem_bytes);
        attr_set = true;
    }

    init_kernel<<<(HID * BATCH + NTHR - 1) / NTHR, NTHR>>>();
    transpose_kernel<<<dim3(SEQ, 2), NTHR>>>(x);
    lstm_persistent<<<NCTA, NTHR, smem_bytes>>>(P);
}

// round 3
// speedup vs baseline: 3.2269x; 3.2269x over previous
#include <cuda_runtime.h>
#include <cuda_bf16.h>
#include <cstdint>
#include <math.h>

// ---------------- problem dims ----------------
#define SEQ   512
#define BATCH 64
#define INPUT 256
#define HID   1024

// ---------------- config ----------------
#define NCTA  128            // 16 m-tiles x 8 k-slices
#define NTHR  256
#define NM    16             // m CTAs (256 gate-rows each)
#define NKS   8              // k slices (160 k each: 128 h + 32 x)
#define RPC   256            // rows per CTA (4 gates x 64 j)
#define KSL   160
#define ASTR  336            // bytes per smem row (160*2 + 16 pad)
#define OFF_AHI 0
#define OFF_ALO (RPC*ASTR)          // 86016
#define OFF_BHI (2*RPC*ASTR)        // 172032
#define OFF_BLO (2*RPC*ASTR + BATCH*ASTR)  // 193536
#define SMEM_TOTAL (2*RPC*ASTR + 2*BATCH*ASTR) // 215040

// ---------------- scratch ----------------
__device__ float    g_h[BATCH * HID];              // h state [b][j]
__device__ float    g_part[NKS * NM * RPC * BATCH]; // partials [ks][m][row][b]
__device__ unsigned g_bar;

struct Params {
    const float* x;
    const float* Wx[4]; const float* bx[4];
    const float* Wh[4]; const float* bh[4];
    float* out;
};

// ---------------- helpers ----------------
__device__ __forceinline__ uint32_t smem_u32(const void* p) {
    uint32_t a;
    asm("{ .reg .u64 t; cvta.to.shared.u64 t, %1; cvt.u32.u64 %0, t; }" : "=r"(a) : "l"(p));
    return a;
}
__device__ __forceinline__ void ldsm4(uint32_t* r, uint32_t addr) {
    asm volatile("ldmatrix.sync.aligned.m8n8.x4.shared.b16 {%0,%1,%2,%3}, [%4];"
        : "=r"(r[0]), "=r"(r[1]), "=r"(r[2]), "=r"(r[3]) : "r"(addr));
}
__device__ __forceinline__ void ldsm2(uint32_t* r, uint32_t addr) {
    asm volatile("ldmatrix.sync.aligned.m8n8.x2.shared.b16 {%0,%1}, [%2];"
        : "=r"(r[0]), "=r"(r[1]) : "r"(addr));
}
__device__ __forceinline__ void mma_bf16(float* d, const uint32_t* a, const uint32_t* b) {
    asm volatile(
        "mma.sync.aligned.m16n8k16.row.col.f32.bf16.bf16.f32 "
        "{%0,%1,%2,%3}, {%4,%5,%6,%7}, {%8,%9}, {%0,%1,%2,%3};"
        : "+f"(d[0]), "+f"(d[1]), "+f"(d[2]), "+f"(d[3])
        : "r"(a[0]), "r"(a[1]), "r"(a[2]), "r"(a[3]), "r"(b[0]), "r"(b[1]));
}
// split float -> (hi, lo) bf16; pack two elements into one b32 (low = first)
__device__ __forceinline__ void split2(float va, float vb, uint32_t& hi, uint32_t& lo) {
    __nv_bfloat16 ha = __float2bfloat16_rn(va);
    __nv_bfloat16 hb = __float2bfloat16_rn(vb);
    float ra = va - __bfloat162float(ha);
    float rb = vb - __bfloat162float(hb);
    __nv_bfloat162 hp; hp.x = ha; hp.y = hb;
    __nv_bfloat162 lp; lp.x = __float2bfloat16_rn(ra); lp.y = __float2bfloat16_rn(rb);
    hi = *(uint32_t*)&hp;
    lo = *(uint32_t*)&lp;
}
__device__ __forceinline__ float sigm(float x) { return 1.0f / (1.0f + __expf(-x)); }

__device__ __forceinline__ void grid_barrier(unsigned target) {
    __syncthreads();
    if (threadIdx.x == 0) {
        __threadfence();
        atomicAdd(&g_bar, 1u);
        while (*((volatile unsigned*)&g_bar) < target) __nanosleep(8);
        __threadfence();
    }
    __syncthreads();
}

// ---------------------------------------------------------------------------
__global__ void init_kernel() {
    int i = blockIdx.x * blockDim.x + threadIdx.x;
    if (i < BATCH * HID) g_h[i] = 0.0f;
    if (i == 0) g_bar = 0u;
}

// ---------------------------------------------------------------------------
__global__ __launch_bounds__(NTHR, 1)
void lstm_mma(Params P) {
    extern __shared__ char smem[];
    const uint32_t sb = smem_u32(smem);

    const int tid  = threadIdx.x;
    const int w    = tid >> 5;
    const int l    = tid & 31;
    const int mcta = blockIdx.x >> 3;   // 0..15
    const int ks   = blockIdx.x & 7;    // 0..7
    const int j0   = mcta * 64;

    // ---- stage weights into smem (hi/lo bf16), once per launch ----
    {
        const int r = tid;              // one row per thread
        const int gate = r >> 6, jl = r & 63, j = j0 + jl;
        const float4* wh = (const float4*)(P.Wh[gate] + (size_t)j * HID + ks * 128);
        const float4* wx = (const float4*)(P.Wx[gate] + (size_t)j * INPUT + ks * 32);
        char* ahi = smem + OFF_AHI + r * ASTR;
        char* alo = smem + OFF_ALO + r * ASTR;
        #pragma unroll 4
        for (int f = 0; f < 40; f++) {
            float4 v = (f < 32) ? wh[f] : wx[f - 32];
            uint32_t h0, l0, h1, l1;
            split2(v.x, v.y, h0, l0);
            split2(v.z, v.w, h1, l1);
            *(uint2*)(ahi + f * 8) = make_uint2(h0, h1);
            *(uint2*)(alo + f * 8) = make_uint2(l0, l1);
        }
    }
    __syncthreads();

    // ---- ldmatrix lane address components ----
    const uint32_t a_row = (uint32_t)(w * 32 + (l & 7) + ((l >> 3) & 1) * 8);
    const uint32_t a_colb = (uint32_t)(((l >> 4) & 1) * 16);          // bytes
    const uint32_t aAddrHi0 = sb + OFF_AHI + a_row * ASTR + a_colb;
    const uint32_t aAddrHi1 = aAddrHi0 + 16 * ASTR;
    const uint32_t aAddrLo0 = aAddrHi0 + (OFF_ALO - OFF_AHI);
    const uint32_t aAddrLo1 = aAddrLo0 + 16 * ASTR;
    const uint32_t b_rowb = (uint32_t)((l & 7) * ASTR);
    const uint32_t b_colb = (uint32_t)(((l >> 3) & 1) * 16);          // bytes
    const uint32_t bAddrHi = sb + OFF_BHI + b_rowb + b_colb;
    const uint32_t bAddrLo = bAddrHi + (OFF_BLO - OFF_BHI);

    // ---- pointwise cell ownership (fixed across t): 2 cells per thread ----
    const int pb  = ks * 8 + (tid & 7);
    const int jlA = tid >> 3;           // 0..31
    const int jlB = jlA + 32;
    const int jA  = j0 + jlA, jB = j0 + jlB;
    float biasA[4], biasB[4];
    #pragma unroll
    for (int g = 0; g < 4; g++) {
        biasA[g] = P.bh[g][jA] + P.bx[g][jA];
        biasB[g] = P.bh[g][jB] + P.bx[g][jB];
    }
    float cA = 0.0f, cB = 0.0f;

    float* out = P.out;
    const size_t BH  = (size_t)BATCH * HID;
    const size_t SBH = (size_t)SEQ * BH;

    // staging index precompute
    const int stb = tid >> 2;           // batch 0..63
    const int stf = tid & 3;            // float4 phase
    const float* hbase = g_h + (size_t)stb * HID + ks * 128;
    char* bhi_row = smem + OFF_BHI + stb * ASTR;
    char* blo_row = smem + OFF_BLO + stb * ASTR;

    float* ppart = g_part + (size_t)(ks * NM + mcta) * RPC * BATCH;

    for (int t = 0; t < SEQ; t++) {
        // ---- stage B (hx hi/lo) ----
        #pragma unroll
        for (int it = 0; it < 8; it++) {                 // h: 32 float4 per batch
            int f = stf + it * 4;                        // 0..31
            float4 v = __ldcg((const float4*)hbase + f);
            uint32_t h0, l0, h1, l1;
            split2(v.x, v.y, h0, l0);
            split2(v.z, v.w, h1, l1);
            *(uint2*)(bhi_row + f * 8) = make_uint2(h0, h1);
            *(uint2*)(blo_row + f * 8) = make_uint2(l0, l1);
        }
        {
            const float4* xb = (const float4*)(P.x + (size_t)t * BATCH * INPUT
                                               + (size_t)stb * INPUT + ks * 32);
            #pragma unroll
            for (int it = 0; it < 2; it++) {             // x: 8 float4 per batch
                int f = stf + it * 4;                    // 0..7
                float4 v = xb[f];
                uint32_t h0, l0, h1, l1;
                split2(v.x, v.y, h0, l0);
                split2(v.z, v.w, h1, l1);
                *(uint2*)(bhi_row + 256 + f * 8) = make_uint2(h0, h1);
                *(uint2*)(blo_row + 256 + f * 8) = make_uint2(l0, l1);
            }
        }
        __syncthreads();

        // ---- GEMM: D[256 rows][64 b] = A(W) * B(hx), 3-pass split bf16 ----
        float d[2][8][4];
        #pragma unroll
        for (int mt = 0; mt < 2; mt++)
            #pragma unroll
            for (int nt = 0; nt < 8; nt++)
                #pragma unroll
                for (int q = 0; q < 4; q++) d[mt][nt][q] = 0.0f;

        for (int kt = 0; kt < 10; kt++) {
            const uint32_t kb = (uint32_t)(kt * 32);     // bytes along k
            uint32_t Ah0[4], Ah1[4], Al0[4], Al1[4];
            ldsm4(Ah0, aAddrHi0 + kb);
            ldsm4(Ah1, aAddrHi1 + kb);
            ldsm4(Al0, aAddrLo0 + kb);
            ldsm4(Al1, aAddrLo1 + kb);
            #pragma unroll
            for (int nt = 0; nt < 8; nt++) {
                uint32_t Bh[2], Bl[2];
                const uint32_t bo = (uint32_t)(nt * 8 * ASTR) + kb;
                ldsm2(Bh, bAddrHi + bo);
                ldsm2(Bl, bAddrLo + bo);
                mma_bf16(d[0][nt], Ah0, Bh);
                mma_bf16(d[1][nt], Ah1, Bh);
                mma_bf16(d[0][nt], Ah0, Bl);
                mma_bf16(d[1][nt], Ah1, Bl);
                mma_bf16(d[0][nt], Al0, Bh);
                mma_bf16(d[1][nt], Al1, Bh);
            }
        }

        // ---- store partials: [row][b] (float2 per reg-pair) ----
        {
            const int r0 = w * 32 + (l >> 2);
            const int c0 = (l & 3) * 2;
            #pragma unroll
            for (int mt = 0; mt < 2; mt++) {
                #pragma unroll
                for (int nt = 0; nt < 8; nt++) {
                    int row = r0 + mt * 16;
                    int col = nt * 8 + c0;
                    *(float2*)(ppart + (size_t)row * BATCH + col) =
                        make_float2(d[mt][nt][0], d[mt][nt][1]);
                    *(float2*)(ppart + (size_t)(row + 8) * BATCH + col) =
                        make_float2(d[mt][nt][2], d[mt][nt][3]);
                }
            }
        }

        grid_barrier((unsigned)(2 * t + 1) * NCTA);

        // ---- reduce 8 k-slices + pointwise (2 cells) ----
        {
            float accA[4], accB[4];
            #pragma unroll
            for (int g = 0; g < 4; g++) { accA[g] = biasA[g]; accB[g] = biasB[g]; }
            #pragma unroll
            for (int g = 0; g < 4; g++) {
                #pragma unroll
                for (int s = 0; s < NKS; s++) {
                    const float* pp = g_part + (size_t)(s * NM + mcta) * RPC * BATCH + pb;
                    accA[g] += __ldcg(pp + (size_t)(g * 64 + jlA) * BATCH);
                    accB[g] += __ldcg(pp + (size_t)(g * 64 + jlB) * BATCH);
                }
            }
            float f, i1, i2, o, hv;

            f = sigm(accA[0]); i1 = sigm(accA[1]); i2 = tanhf(accA[2]); o = sigm(accA[3]);
            cA = cA * f + i1 * i2;
            hv = tanhf(cA) * o;
            out[(size_t)t * BH + (size_t)pb * HID + jA] = hv;
            g_h[(size_t)pb * HID + jA] = hv;
            if (t == SEQ - 1) {
                out[SBH + (size_t)pb * HID + jA] = hv;
                out[SBH + BH + (size_t)pb * HID + jA] = cA;
            }

            f = sigm(accB[0]); i1 = sigm(accB[1]); i2 = tanhf(accB[2]); o = sigm(accB[3]);
            cB = cB * f + i1 * i2;
            hv = tanhf(cB) * o;
            out[(size_t)t * BH + (size_t)pb * HID + jB] = hv;
            g_h[(size_t)pb * HID + jB] = hv;
            if (t == SEQ - 1) {
                out[SBH + (size_t)pb * HID + jB] = hv;
                out[SBH + BH + (size_t)pb * HID + jB] = cB;
            }
        }

        grid_barrier((unsigned)(2 * t + 2) * NCTA);
    }
}

// ---------------------------------------------------------------------------
extern "C" void kernel_launch(void* const* d_in, const int* in_sizes, int n_in,
                              void* d_out, int out_size) {
    Params P;
    P.x = (const float*)d_in[0];
    P.Wx[0] = (const float*)d_in[1];  P.bx[0] = (const float*)d_in[2];
    P.Wx[1] = (const float*)d_in[3];  P.bx[1] = (const float*)d_in[4];
    P.Wx[2] = (const float*)d_in[5];  P.bx[2] = (const float*)d_in[6];
    P.Wx[3] = (const float*)d_in[7];  P.bx[3] = (const float*)d_in[8];
    P.Wh[0] = (const float*)d_in[9];  P.bh[0] = (const float*)d_in[10];
    P.Wh[1] = (const float*)d_in[11]; P.bh[1] = (const float*)d_in[12];
    P.Wh[2] = (const float*)d_in[13]; P.bh[2] = (const float*)d_in[14];
    P.Wh[3] = (const float*)d_in[15]; P.bh[3] = (const float*)d_in[16];
    P.out   = (float*)d_out;

    static bool attr_set = false;
    if (!attr_set) {
        cudaFuncSetAttribute(lstm_mma, cudaFuncAttributeMaxDynamicSharedMemorySize,
                             SMEM_TOTAL);
        attr_set = true;
    }

    init_kernel<<<(BATCH * HID + NTHR - 1) / NTHR, NTHR>>>();
    lstm_mma<<<NCTA, NTHR, SMEM_TOTAL>>>(P);
}